// round 4
// baseline (speedup 1.0000x reference)
#include <cuda_runtime.h>
#include <math.h>
#include <stdint.h>

constexpr int H    = 128;
constexpr int G4   = 512;
constexpr int B    = 512;
constexpr int T    = 128;
constexpr int S    = 1536;   // 3 inputs * B
constexpr int NB   = 12;     // seqs per block
constexpr int NSG  = 6;      // seqs per 256-thread group
constexpr int NBLK = 128;
constexpr int NTH  = 512;

__device__ float4 g_Wq1hh[64 * 256];
__device__ float4 g_Wq2ih[64 * 256];
__device__ float4 g_Wq2hh[64 * 256];
__device__ float2 g_b1p[256];
__device__ float2 g_b2p[256];
__device__ float2 g_wx1p[256 * 5];
__device__ float  g_out1[(size_t)S * T * H];
__device__ float  g_lasth[S * H];
__device__ float  g_ps1[S * H];
__device__ float  g_pq1[S * H];
__device__ float  g_ps2[S * H];
__device__ float  g_pq2[S * H];
__device__ float2 g_bn1[3 * H];
__device__ float2 g_bn2[3 * H];

typedef unsigned long long ull;

__device__ __forceinline__ ull pk2(float x, float y) {
    ull r;
    asm("mov.b64 %0, {%1,%2};" : "=l"(r) : "r"(__float_as_uint(x)), "r"(__float_as_uint(y)));
    return r;
}
__device__ __forceinline__ float2 upk2(ull v) {
    unsigned lo, hi;
    asm("mov.b64 {%0,%1}, %2;" : "=r"(lo), "=r"(hi) : "l"(v));
    return make_float2(__uint_as_float(lo), __uint_as_float(hi));
}
__device__ __forceinline__ ull ffma2(ull a, ull b, ull c) {
    ull d;
    asm("fma.rn.f32x2 %0, %1, %2, %3;" : "=l"(d) : "l"(a), "l"(b), "l"(c));
    return d;
}
__device__ __forceinline__ float sigm(float x) {
    return __fdividef(1.f, 1.f + __expf(-x));
}
__device__ __forceinline__ float tanh_f(float x) {
    float e = __expf(-2.f * fabsf(x));
    float t = __fdividef(1.f - e, 1.f + e);
    return copysignf(t, x);
}

// ---------- pack weights for FFMA2 ----------
__global__ void prep_kernel(const float* Wih1, const float* Whh1, const float* bih1, const float* bhh1,
                            const float* Wih2, const float* Whh2, const float* bih2, const float* bhh2) {
    int tid = blockIdx.x * blockDim.x + threadIdx.x;
    int stride = gridDim.x * blockDim.x;
    for (int idx = tid; idx < 64 * 256; idx += stride) {
        int k2 = idx >> 8, jp = idx & 255;
        int j0 = 2 * jp, j1 = j0 + 1, k0 = 2 * k2, k1 = k0 + 1;
        g_Wq1hh[idx] = make_float4(Whh1[j0*H+k0], Whh1[j1*H+k0], Whh1[j0*H+k1], Whh1[j1*H+k1]);
        g_Wq2ih[idx] = make_float4(Wih2[j0*H+k0], Wih2[j1*H+k0], Wih2[j0*H+k1], Wih2[j1*H+k1]);
        g_Wq2hh[idx] = make_float4(Whh2[j0*H+k0], Whh2[j1*H+k0], Whh2[j0*H+k1], Whh2[j1*H+k1]);
    }
    for (int jp = tid; jp < 256; jp += stride) {
        int j0 = 2 * jp, j1 = j0 + 1;
        g_b1p[jp] = make_float2(bih1[j0] + bhh1[j0], bih1[j1] + bhh1[j1]);
        g_b2p[jp] = make_float2(bih2[j0] + bhh2[j0], bih2[j1] + bhh2[j1]);
        for (int d = 0; d < 5; d++)
            g_wx1p[jp * 5 + d] = make_float2(Wih1[j0*5+d], Wih1[j1*5+d]);
    }
}

// ---------- layer 1 LSTM ----------
__global__ void __launch_bounds__(NTH, 1)
lstm1_kernel(const float* __restrict__ xa, const float* __restrict__ xp, const float* __restrict__ xn) {
    __shared__ __align__(16) float2 hp[NB][H];
    __shared__ float2 xps[NB][5];
    __shared__ float  act[NB][G4];

    const int tid = threadIdx.x;
    const int jp  = tid & 255;
    const int g6  = (tid >> 8) * NSG;
    const int sbase = blockIdx.x * NB;

    float2 bs = g_b1p[jp];
    const ull biasp = pk2(bs.x, bs.y);
    ull wx[5];
#pragma unroll
    for (int d = 0; d < 5; d++) { float2 w = g_wx1p[jp*5+d]; wx[d] = pk2(w.x, w.y); }

    int ts[3], tm[3];
    float csr[3] = {0,0,0}, sum[3] = {0,0,0}, sq[3] = {0,0,0};
#pragma unroll
    for (int r = 0; r < 3; r++) { int u = tid + NTH*r; ts[r] = u >> 7; tm[r] = u & 127; }

    const float* xptr = xa; int xoff = 0, xsl = 0, xd = 0;
    if (tid < NB * 5) {
        xsl = tid / 5; xd = tid % 5;
        int s = sbase + xsl, in = s >> 9, b = s & 511;
        xptr = (in == 0) ? xa : ((in == 1) ? xp : xn);
        xoff = b * (T * 5) + xd;
    }
    {
        float2* f = &hp[0][0];
#pragma unroll
        for (int r = 0; r < 3; r++) f[tid + NTH*r] = make_float2(0.f, 0.f);
    }
    __syncthreads();

    for (int t = 0; t < T; t++) {
        if (tid < NB * 5) {
            float v = __ldg(&xptr[xoff + t * 5]);
            xps[xsl][xd] = make_float2(v, v);
        }
        __syncthreads();

        ull acc[NSG];
#pragma unroll
        for (int sl = 0; sl < NSG; sl++) acc[sl] = biasp;
#pragma unroll
        for (int d = 0; d < 5; d++)
#pragma unroll
            for (int sl = 0; sl < NSG; sl++)
                acc[sl] = ffma2(wx[d], *(const ull*)&xps[g6+sl][d], acc[sl]);
#pragma unroll 2
        for (int k2 = 0; k2 < 64; k2++) {
            float4 w = __ldg(&g_Wq1hh[(k2 << 8) + jp]);
            ull wlo = pk2(w.x, w.y), whi = pk2(w.z, w.w);
            ulonglong2 hv[NSG];
#pragma unroll
            for (int sl = 0; sl < NSG; sl++)
                hv[sl] = *(const ulonglong2*)&hp[g6+sl][2*k2];
#pragma unroll
            for (int sl = 0; sl < NSG; sl++) acc[sl] = ffma2(wlo, hv[sl].x, acc[sl]);
#pragma unroll
            for (int sl = 0; sl < NSG; sl++) acc[sl] = ffma2(whi, hv[sl].y, acc[sl]);
        }
        const int gt = jp >> 6;
#pragma unroll
        for (int sl = 0; sl < NSG; sl++) {
            float2 v = upk2(acc[sl]);
            float a0, a1;
            if (gt == 2) { a0 = tanh_f(v.x); a1 = tanh_f(v.y); }
            else         { a0 = sigm(v.x);   a1 = sigm(v.y); }
            *(float2*)&act[g6+sl][2*jp] = make_float2(a0, a1);
        }
        __syncthreads();

#pragma unroll
        for (int r = 0; r < 3; r++) {
            int s = ts[r], m = tm[r];
            float gi = act[s][m], gf = act[s][m+128], gg = act[s][m+256], go = act[s][m+384];
            float c = fmaf(gf, csr[r], gi * gg);
            csr[r] = c;
            float h = go * tanh_f(c);
            hp[s][m] = make_float2(h, h);
            g_out1[((size_t)(sbase + s) * T + t) * H + m] = h;
            sum[r] += h;
            sq[r] = fmaf(h, h, sq[r]);
        }
        __syncthreads();
    }
#pragma unroll
    for (int r = 0; r < 3; r++) {
        int idx = (sbase + ts[r]) * H + tm[r];
        g_ps1[idx] = sum[r];
        g_pq1[idx] = sq[r];
    }
}

// ---------- BN stats reduce (fp64, deterministic) ----------
__global__ void bn_reduce_kernel(const float* __restrict__ ps, const float* __restrict__ pq,
                                 const float* __restrict__ gamma, const float* __restrict__ beta,
                                 float2* __restrict__ bnout) {
    int tid = threadIdx.x;            // 0..383 : in*H + c
    if (tid >= 3 * H) return;
    int in = tid >> 7, c = tid & 127;
    double s = 0.0, q = 0.0;
    int base = in * B;
    for (int b = 0; b < B; b++) {
        s += (double)ps[(base + b) * H + c];
        q += (double)pq[(base + b) * H + c];
    }
    double n = (double)B * T;
    double mean = s / n;
    double var = q / n - mean * mean;
    float scale = gamma[c] * (float)rsqrt(var + 1e-5);
    float shift = beta[c] - (float)mean * scale;
    bnout[tid] = make_float2(scale, shift);
}

// ---------- layer 2 LSTM (BN1 + Wih2*x folded, K=256) ----------
__global__ void __launch_bounds__(NTH, 1)
lstm2_kernel() {
    __shared__ __align__(16) float2 hp[NB][H];
    __shared__ __align__(16) float2 xq[NB][H];
    __shared__ float act[NB][G4];

    const int tid = threadIdx.x;
    const int jp  = tid & 255;
    const int g6  = (tid >> 8) * NSG;
    const int sbase = blockIdx.x * NB;

    float2 bs = g_b2p[jp];
    const ull biasp = pk2(bs.x, bs.y);

    int ts[3], tm[3];
    float sc[3], sh[3];
    float csr[3] = {0,0,0}, sum[3] = {0,0,0}, sq[3] = {0,0,0};
#pragma unroll
    for (int r = 0; r < 3; r++) {
        int u = tid + NTH*r; ts[r] = u >> 7; tm[r] = u & 127;
        int in = (sbase + ts[r]) >> 9;
        float2 bn = g_bn1[in * H + tm[r]];
        sc[r] = bn.x; sh[r] = bn.y;
    }
    {
        float2* f = &hp[0][0];
#pragma unroll
        for (int r = 0; r < 3; r++) f[tid + NTH*r] = make_float2(0.f, 0.f);
    }
    __syncthreads();

    for (int t = 0; t < T; t++) {
#pragma unroll
        for (int r = 0; r < 3; r++) {
            int s = ts[r], m = tm[r];
            float o = g_out1[((size_t)(sbase + s) * T + t) * H + m];
            float xv = fmaf(o, sc[r], sh[r]);
            xq[s][m] = make_float2(xv, xv);
        }
        __syncthreads();

        ull acc[NSG];
#pragma unroll
        for (int sl = 0; sl < NSG; sl++) acc[sl] = biasp;
#pragma unroll 2
        for (int k2 = 0; k2 < 64; k2++) {
            float4 w = __ldg(&g_Wq2ih[(k2 << 8) + jp]);
            ull wlo = pk2(w.x, w.y), whi = pk2(w.z, w.w);
            ulonglong2 hv[NSG];
#pragma unroll
            for (int sl = 0; sl < NSG; sl++)
                hv[sl] = *(const ulonglong2*)&xq[g6+sl][2*k2];
#pragma unroll
            for (int sl = 0; sl < NSG; sl++) acc[sl] = ffma2(wlo, hv[sl].x, acc[sl]);
#pragma unroll
            for (int sl = 0; sl < NSG; sl++) acc[sl] = ffma2(whi, hv[sl].y, acc[sl]);
        }
#pragma unroll 2
        for (int k2 = 0; k2 < 64; k2++) {
            float4 w = __ldg(&g_Wq2hh[(k2 << 8) + jp]);
            ull wlo = pk2(w.x, w.y), whi = pk2(w.z, w.w);
            ulonglong2 hv[NSG];
#pragma unroll
            for (int sl = 0; sl < NSG; sl++)
                hv[sl] = *(const ulonglong2*)&hp[g6+sl][2*k2];
#pragma unroll
            for (int sl = 0; sl < NSG; sl++) acc[sl] = ffma2(wlo, hv[sl].x, acc[sl]);
#pragma unroll
            for (int sl = 0; sl < NSG; sl++) acc[sl] = ffma2(whi, hv[sl].y, acc[sl]);
        }
        const int gt = jp >> 6;
#pragma unroll
        for (int sl = 0; sl < NSG; sl++) {
            float2 v = upk2(acc[sl]);
            float a0, a1;
            if (gt == 2) { a0 = tanh_f(v.x); a1 = tanh_f(v.y); }
            else         { a0 = sigm(v.x);   a1 = sigm(v.y); }
            *(float2*)&act[g6+sl][2*jp] = make_float2(a0, a1);
        }
        __syncthreads();

#pragma unroll
        for (int r = 0; r < 3; r++) {
            int s = ts[r], m = tm[r];
            float gi = act[s][m], gf = act[s][m+128], gg = act[s][m+256], go = act[s][m+384];
            float c = fmaf(gf, csr[r], gi * gg);
            csr[r] = c;
            float h = go * tanh_f(c);
            hp[s][m] = make_float2(h, h);
            sum[r] += h;
            sq[r] = fmaf(h, h, sq[r]);
            if (t == T - 1) g_lasth[(sbase + s) * H + m] = h;
        }
        __syncthreads();
    }
#pragma unroll
    for (int r = 0; r < 3; r++) {
        int idx = (sbase + ts[r]) * H + tm[r];
        g_ps2[idx] = sum[r];
        g_pq2[idx] = sq[r];
    }
}

// ---------- FC + L2 normalize ----------
__global__ void __launch_bounds__(128)
final_kernel(const float* __restrict__ fcW, const float* __restrict__ fcb, float* __restrict__ out) {
    __shared__ float xn[H];
    __shared__ float emb[H];
    __shared__ float red[128];
    int s = blockIdx.x, j = threadIdx.x;
    int in = s >> 9, b = s & 511;

    float2 bn = g_bn2[in * H + j];
    xn[j] = fmaf(g_lasth[s * H + j], bn.x, bn.y);
    __syncthreads();

    float e = fcb[j];
    const float* wrow = fcW + j * H;
#pragma unroll 4
    for (int k = 0; k < H; k++) e = fmaf(__ldg(&wrow[k]), xn[k], e);
    emb[j] = e;
    red[j] = e * e;
    __syncthreads();
    for (int off = 64; off > 0; off >>= 1) {
        if (j < off) red[j] += red[j + off];
        __syncthreads();
    }
    float norm = sqrtf(red[0]);
    float inv = 1.f / fmaxf(norm, 1e-12f);
    out[((size_t)in * B + b) * H + j] = emb[j] * inv;
}

extern "C" void kernel_launch(void* const* d_in, const int* in_sizes, int n_in,
                              void* d_out, int out_size) {
    const float* a    = (const float*)d_in[0];
    const float* p    = (const float*)d_in[1];
    const float* n    = (const float*)d_in[2];
    const float* Wih1 = (const float*)d_in[3];
    const float* Whh1 = (const float*)d_in[4];
    const float* bih1 = (const float*)d_in[5];
    const float* bhh1 = (const float*)d_in[6];
    const float* g1   = (const float*)d_in[7];
    const float* b1   = (const float*)d_in[8];
    const float* Wih2 = (const float*)d_in[9];
    const float* Whh2 = (const float*)d_in[10];
    const float* bih2 = (const float*)d_in[11];
    const float* bhh2 = (const float*)d_in[12];
    const float* g2   = (const float*)d_in[13];
    const float* b2   = (const float*)d_in[14];
    const float* fcW  = (const float*)d_in[15];
    const float* fcb  = (const float*)d_in[16];
    float* out = (float*)d_out;

    float2 *bn1p, *bn2p;
    cudaGetSymbolAddress((void**)&bn1p, g_bn1);
    cudaGetSymbolAddress((void**)&bn2p, g_bn2);
    float *ps1, *pq1, *ps2, *pq2;
    cudaGetSymbolAddress((void**)&ps1, g_ps1);
    cudaGetSymbolAddress((void**)&pq1, g_pq1);
    cudaGetSymbolAddress((void**)&ps2, g_ps2);
    cudaGetSymbolAddress((void**)&pq2, g_pq2);

    prep_kernel<<<64, 256>>>(Wih1, Whh1, bih1, bhh1, Wih2, Whh2, bih2, bhh2);
    lstm1_kernel<<<NBLK, NTH>>>(a, p, n);
    bn_reduce_kernel<<<1, 384>>>(ps1, pq1, g1, b1, bn1p);
    lstm2_kernel<<<NBLK, NTH>>>();
    bn_reduce_kernel<<<1, 384>>>(ps2, pq2, g2, b2, bn2p);
    final_kernel<<<S, 128>>>(fcW, fcb, out);
}

// round 5
// speedup vs baseline: 1.2931x; 1.2931x over previous
#include <cuda_runtime.h>
#include <math.h>
#include <stdint.h>

constexpr int H    = 128;
constexpr int G4   = 512;
constexpr int B    = 512;
constexpr int T    = 128;
constexpr int S    = 1536;   // 3 inputs * B
constexpr int NB   = 12;     // seqs per block
constexpr int NBLK = 128;
constexpr int NTH  = 256;

// k4-major packed weights: g_W[k4*512 + j] = {W[j][4k4], W[j][4k4+1], W[j][4k4+2], W[j][4k4+3]}
__device__ float4 g_W1h[32 * 512];
__device__ float4 g_W2i[32 * 512];
__device__ float4 g_W2h[32 * 512];
__device__ float  g_b1[512];
__device__ float  g_b2[512];
__device__ float  g_wx1[5 * 512];          // [d][j]
__device__ float  g_out1[(size_t)S * T * H];
__device__ float  g_lasth[S * H];
__device__ float  g_ps1[S * H];
__device__ float  g_pq1[S * H];
__device__ float  g_ps2[S * H];
__device__ float  g_pq2[S * H];
__device__ float2 g_bn1[3 * H];
__device__ float2 g_bn2[3 * H];

typedef unsigned long long ull;

__device__ __forceinline__ ull pk2(float x, float y) {
    ull r;
    asm("mov.b64 %0, {%1,%2};" : "=l"(r) : "r"(__float_as_uint(x)), "r"(__float_as_uint(y)));
    return r;
}
__device__ __forceinline__ float2 upk2(ull v) {
    unsigned lo, hi;
    asm("mov.b64 {%0,%1}, %2;" : "=r"(lo), "=r"(hi) : "l"(v));
    return make_float2(__uint_as_float(lo), __uint_as_float(hi));
}
__device__ __forceinline__ ull ffma2(ull a, ull b, ull c) {
    ull d;
    asm("fma.rn.f32x2 %0, %1, %2, %3;" : "=l"(d) : "l"(a), "l"(b), "l"(c));
    return d;
}
__device__ __forceinline__ float sigm(float x) {
    return __fdividef(1.f, 1.f + __expf(-x));
}
__device__ __forceinline__ float tanh_f(float x) {
    float e = __expf(-2.f * fabsf(x));
    float t = __fdividef(1.f - e, 1.f + e);
    return copysignf(t, x);
}

// ---------- pack weights ----------
__global__ void prep_kernel(const float* Wih1, const float* Whh1, const float* bih1, const float* bhh1,
                            const float* Wih2, const float* Whh2, const float* bih2, const float* bhh2) {
    int tid = blockIdx.x * blockDim.x + threadIdx.x;
    int stride = gridDim.x * blockDim.x;
    for (int idx = tid; idx < 32 * 512; idx += stride) {
        int k4 = idx >> 9, j = idx & 511;
        g_W1h[idx] = *(const float4*)&Whh1[j * H + 4 * k4];
        g_W2i[idx] = *(const float4*)&Wih2[j * H + 4 * k4];
        g_W2h[idx] = *(const float4*)&Whh2[j * H + 4 * k4];
    }
    for (int j = tid; j < 512; j += stride) {
        g_b1[j] = bih1[j] + bhh1[j];
        g_b2[j] = bih2[j] + bhh2[j];
        for (int d = 0; d < 5; d++) g_wx1[d * 512 + j] = Wih1[j * 5 + d];
    }
}

// ---------- layer 1 LSTM : 128 blocks x 256 thr, 12 seqs/block ----------
__global__ void __launch_bounds__(NTH, 1)
lstm1_kernel(const float* __restrict__ xa, const float* __restrict__ xp, const float* __restrict__ xn) {
    __shared__ __align__(16) float hp[NB][H];    // 6 KB
    __shared__ float act[NB][G4];                // 24 KB
    __shared__ float xps[NB][5];

    const int tid = threadIdx.x;
    const int j0 = tid, j1 = tid + 256;
    const int sbase = blockIdx.x * NB;

    const float bias0 = g_b1[j0];
    const float bias1 = g_b1[j1];
    float wx0[5], wx1[5];
#pragma unroll
    for (int d = 0; d < 5; d++) { wx0[d] = g_wx1[d * 512 + j0]; wx1[d] = g_wx1[d * 512 + j1]; }

    // phase-2 mapping: slot r -> seq s = (tid>>7) + 2r, channel m = tid & 127
    const int m  = tid & 127;
    const int sb = tid >> 7;
    float csr[6] = {0,0,0,0,0,0}, sum[6] = {0,0,0,0,0,0}, sq[6] = {0,0,0,0,0,0};

    // x loader (threads 0..59)
    const float* xptr = xa; int xoff = 0, xsl = 0, xd = 0;
    if (tid < NB * 5) {
        xsl = tid / 5; xd = tid - 5 * xsl;
        int s = sbase + xsl, in = s >> 9, b = s & 511;
        xptr = (in == 0) ? xa : ((in == 1) ? xp : xn);
        xoff = b * (T * 5) + xd;
    }
    {
        float* f = &hp[0][0];
#pragma unroll
        for (int r = 0; r < 6; r++) f[tid + NTH * r] = 0.f;
    }
    __syncthreads();

    for (int t = 0; t < T; t++) {
        if (tid < NB * 5) xps[xsl][xd] = __ldg(&xptr[xoff + t * 5]);
        __syncthreads();

        ull acc0[NB], acc1[NB];
#pragma unroll
        for (int s = 0; s < NB; s++) {
            float d0 = bias0, d1 = bias1;
#pragma unroll
            for (int d = 0; d < 5; d++) {
                float xv = xps[s][d];
                d0 = fmaf(wx0[d], xv, d0);
                d1 = fmaf(wx1[d], xv, d1);
            }
            acc0[s] = pk2(d0, 0.f);
            acc1[s] = pk2(d1, 0.f);
        }
#pragma unroll 2
        for (int k4 = 0; k4 < 32; k4++) {
            float4 w0 = __ldg(&g_W1h[(k4 << 9) + j0]);
            float4 w1 = __ldg(&g_W1h[(k4 << 9) + j1]);
            ull w0lo = pk2(w0.x, w0.y), w0hi = pk2(w0.z, w0.w);
            ull w1lo = pk2(w1.x, w1.y), w1hi = pk2(w1.z, w1.w);
            ulonglong2 hv[NB];
#pragma unroll
            for (int s = 0; s < NB; s++) hv[s] = *(const ulonglong2*)&hp[s][4 * k4];
#pragma unroll
            for (int s = 0; s < NB; s++) {
                acc0[s] = ffma2(w0lo, hv[s].x, acc0[s]);
                acc0[s] = ffma2(w0hi, hv[s].y, acc0[s]);
                acc1[s] = ffma2(w1lo, hv[s].x, acc1[s]);
                acc1[s] = ffma2(w1hi, hv[s].y, acc1[s]);
            }
        }
        // j0 in [0,256): i/f gates -> sigmoid; j1 in [256,512): g -> tanh, o -> sigmoid
        const bool j1_tanh = (tid < 128);
#pragma unroll
        for (int s = 0; s < NB; s++) {
            float2 v0 = upk2(acc0[s]);
            float2 v1 = upk2(acc1[s]);
            float z0 = v0.x + v0.y, z1 = v1.x + v1.y;
            act[s][j0] = sigm(z0);
            act[s][j1] = j1_tanh ? tanh_f(z1) : sigm(z1);
        }
        __syncthreads();

#pragma unroll
        for (int r = 0; r < 6; r++) {
            int s = sb + 2 * r;
            float gi = act[s][m], gf = act[s][m + 128], gg = act[s][m + 256], go = act[s][m + 384];
            float c = fmaf(gf, csr[r], gi * gg);
            csr[r] = c;
            float h = go * tanh_f(c);
            hp[s][m] = h;
            g_out1[((size_t)(sbase + s) * T + t) * H + m] = h;
            sum[r] += h;
            sq[r] = fmaf(h, h, sq[r]);
        }
        __syncthreads();
    }
#pragma unroll
    for (int r = 0; r < 6; r++) {
        int idx = (sbase + sb + 2 * r) * H + m;
        g_ps1[idx] = sum[r];
        g_pq1[idx] = sq[r];
    }
}

// ---------- BN stats reduce (fp64 tree, deterministic) ----------
__global__ void __launch_bounds__(128)
bn_reduce_kernel(const float* __restrict__ ps, const float* __restrict__ pq,
                 const float* __restrict__ gamma, const float* __restrict__ beta,
                 float2* __restrict__ bnout) {
    __shared__ double rs[128], rq[128];
    int cidx = blockIdx.x;               // in*H + c
    int in = cidx >> 7, c = cidx & 127;
    int t = threadIdx.x;
    double s = 0.0, q = 0.0;
    for (int b = t; b < B; b += 128) {
        int idx = (in * B + b) * H + c;
        s += (double)ps[idx];
        q += (double)pq[idx];
    }
    rs[t] = s; rq[t] = q;
    __syncthreads();
    for (int off = 64; off > 0; off >>= 1) {
        if (t < off) { rs[t] += rs[t + off]; rq[t] += rq[t + off]; }
        __syncthreads();
    }
    if (t == 0) {
        double n = (double)B * T;
        double mean = rs[0] / n;
        double var = rq[0] / n - mean * mean;
        float scale = gamma[c] * (float)rsqrt(var + 1e-5);
        float shift = beta[c] - (float)mean * scale;
        bnout[cidx] = make_float2(scale, shift);
    }
}

// ---------- layer 2 LSTM (BN1 + Wih2*x folded, K=256) ----------
__global__ void __launch_bounds__(NTH, 1)
lstm2_kernel() {
    __shared__ __align__(16) float hp[NB][H];
    __shared__ __align__(16) float xq[NB][H];
    __shared__ float act[NB][G4];

    const int tid = threadIdx.x;
    const int j0 = tid, j1 = tid + 256;
    const int sbase = blockIdx.x * NB;

    const float bias0 = g_b2[j0];
    const float bias1 = g_b2[j1];

    const int m  = tid & 127;
    const int sb = tid >> 7;
    float sc[6], sh[6];
    float csr[6] = {0,0,0,0,0,0}, sum[6] = {0,0,0,0,0,0}, sq[6] = {0,0,0,0,0,0};
#pragma unroll
    for (int r = 0; r < 6; r++) {
        int in = (sbase + sb + 2 * r) >> 9;
        float2 bn = g_bn1[in * H + m];
        sc[r] = bn.x; sh[r] = bn.y;
    }
    {
        float* f = &hp[0][0];
#pragma unroll
        for (int r = 0; r < 6; r++) f[tid + NTH * r] = 0.f;
    }
    __syncthreads();

    for (int t = 0; t < T; t++) {
#pragma unroll
        for (int r = 0; r < 6; r++) {
            int s = sb + 2 * r;
            float o = g_out1[((size_t)(sbase + s) * T + t) * H + m];
            xq[s][m] = fmaf(o, sc[r], sh[r]);
        }
        __syncthreads();

        ull acc0[NB], acc1[NB];
#pragma unroll
        for (int s = 0; s < NB; s++) { acc0[s] = pk2(bias0, 0.f); acc1[s] = pk2(bias1, 0.f); }

#pragma unroll 2
        for (int k4 = 0; k4 < 32; k4++) {
            float4 w0 = __ldg(&g_W2i[(k4 << 9) + j0]);
            float4 w1 = __ldg(&g_W2i[(k4 << 9) + j1]);
            ull w0lo = pk2(w0.x, w0.y), w0hi = pk2(w0.z, w0.w);
            ull w1lo = pk2(w1.x, w1.y), w1hi = pk2(w1.z, w1.w);
            ulonglong2 hv[NB];
#pragma unroll
            for (int s = 0; s < NB; s++) hv[s] = *(const ulonglong2*)&xq[s][4 * k4];
#pragma unroll
            for (int s = 0; s < NB; s++) {
                acc0[s] = ffma2(w0lo, hv[s].x, acc0[s]);
                acc0[s] = ffma2(w0hi, hv[s].y, acc0[s]);
                acc1[s] = ffma2(w1lo, hv[s].x, acc1[s]);
                acc1[s] = ffma2(w1hi, hv[s].y, acc1[s]);
            }
        }
#pragma unroll 2
        for (int k4 = 0; k4 < 32; k4++) {
            float4 w0 = __ldg(&g_W2h[(k4 << 9) + j0]);
            float4 w1 = __ldg(&g_W2h[(k4 << 9) + j1]);
            ull w0lo = pk2(w0.x, w0.y), w0hi = pk2(w0.z, w0.w);
            ull w1lo = pk2(w1.x, w1.y), w1hi = pk2(w1.z, w1.w);
            ulonglong2 hv[NB];
#pragma unroll
            for (int s = 0; s < NB; s++) hv[s] = *(const ulonglong2*)&hp[s][4 * k4];
#pragma unroll
            for (int s = 0; s < NB; s++) {
                acc0[s] = ffma2(w0lo, hv[s].x, acc0[s]);
                acc0[s] = ffma2(w0hi, hv[s].y, acc0[s]);
                acc1[s] = ffma2(w1lo, hv[s].x, acc1[s]);
                acc1[s] = ffma2(w1hi, hv[s].y, acc1[s]);
            }
        }
        const bool j1_tanh = (tid < 128);
#pragma unroll
        for (int s = 0; s < NB; s++) {
            float2 v0 = upk2(acc0[s]);
            float2 v1 = upk2(acc1[s]);
            float z0 = v0.x + v0.y, z1 = v1.x + v1.y;
            act[s][j0] = sigm(z0);
            act[s][j1] = j1_tanh ? tanh_f(z1) : sigm(z1);
        }
        __syncthreads();

#pragma unroll
        for (int r = 0; r < 6; r++) {
            int s = sb + 2 * r;
            float gi = act[s][m], gf = act[s][m + 128], gg = act[s][m + 256], go = act[s][m + 384];
            float c = fmaf(gf, csr[r], gi * gg);
            csr[r] = c;
            float h = go * tanh_f(c);
            hp[s][m] = h;
            sum[r] += h;
            sq[r] = fmaf(h, h, sq[r]);
            if (t == T - 1) g_lasth[(sbase + s) * H + m] = h;
        }
        __syncthreads();
    }
#pragma unroll
    for (int r = 0; r < 6; r++) {
        int idx = (sbase + sb + 2 * r) * H + m;
        g_ps2[idx] = sum[r];
        g_pq2[idx] = sq[r];
    }
}

// ---------- FC + L2 normalize ----------
__global__ void __launch_bounds__(128)
final_kernel(const float* __restrict__ fcW, const float* __restrict__ fcb, float* __restrict__ out) {
    __shared__ float xn[H];
    __shared__ float emb[H];
    __shared__ float red[128];
    int s = blockIdx.x, j = threadIdx.x;
    int in = s >> 9, b = s & 511;

    float2 bn = g_bn2[in * H + j];
    xn[j] = fmaf(g_lasth[s * H + j], bn.x, bn.y);
    __syncthreads();

    float e = fcb[j];
    const float* wrow = fcW + j * H;
#pragma unroll 4
    for (int k = 0; k < H; k++) e = fmaf(__ldg(&wrow[k]), xn[k], e);
    emb[j] = e;
    red[j] = e * e;
    __syncthreads();
    for (int off = 64; off > 0; off >>= 1) {
        if (j < off) red[j] += red[j + off];
        __syncthreads();
    }
    float norm = sqrtf(red[0]);
    float inv = 1.f / fmaxf(norm, 1e-12f);
    out[((size_t)in * B + b) * H + j] = emb[j] * inv;
}

extern "C" void kernel_launch(void* const* d_in, const int* in_sizes, int n_in,
                              void* d_out, int out_size) {
    const float* a    = (const float*)d_in[0];
    const float* p    = (const float*)d_in[1];
    const float* n    = (const float*)d_in[2];
    const float* Wih1 = (const float*)d_in[3];
    const float* Whh1 = (const float*)d_in[4];
    const float* bih1 = (const float*)d_in[5];
    const float* bhh1 = (const float*)d_in[6];
    const float* g1   = (const float*)d_in[7];
    const float* b1   = (const float*)d_in[8];
    const float* Wih2 = (const float*)d_in[9];
    const float* Whh2 = (const float*)d_in[10];
    const float* bih2 = (const float*)d_in[11];
    const float* bhh2 = (const float*)d_in[12];
    const float* g2   = (const float*)d_in[13];
    const float* b2   = (const float*)d_in[14];
    const float* fcW  = (const float*)d_in[15];
    const float* fcb  = (const float*)d_in[16];
    float* out = (float*)d_out;

    float2 *bn1p, *bn2p;
    cudaGetSymbolAddress((void**)&bn1p, g_bn1);
    cudaGetSymbolAddress((void**)&bn2p, g_bn2);
    float *ps1, *pq1, *ps2, *pq2;
    cudaGetSymbolAddress((void**)&ps1, g_ps1);
    cudaGetSymbolAddress((void**)&pq1, g_pq1);
    cudaGetSymbolAddress((void**)&ps2, g_ps2);
    cudaGetSymbolAddress((void**)&pq2, g_pq2);

    prep_kernel<<<64, 256>>>(Wih1, Whh1, bih1, bhh1, Wih2, Whh2, bih2, bhh2);
    lstm1_kernel<<<NBLK, NTH>>>(a, p, n);
    bn_reduce_kernel<<<3 * H, 128>>>(ps1, pq1, g1, b1, bn1p);
    lstm2_kernel<<<NBLK, NTH>>>();
    bn_reduce_kernel<<<3 * H, 128>>>(ps2, pq2, g2, b2, bn2p);
    final_kernel<<<S, 128>>>(fcW, fcb, out);
}